// round 4
// baseline (speedup 1.0000x reference)
#include <cuda_runtime.h>
#include <math.h>
#include <stdint.h>

#define B_   2
#define S_   2048
#define H_   2048
#define NH_  16
#define HD_  128
#define NE_  8
#define I_   4096
#define T_   (B_*S_)
#define EPS_ 1e-5f
#define ATT_SCALE 0.08838834764831845f

// -------------------- scratch --------------------
__device__ float g_xn [(size_t)T_*H_];
__device__ float g_q  [(size_t)T_*H_];
__device__ float g_k  [(size_t)T_*H_];
__device__ float g_v  [(size_t)T_*H_];
__device__ float g_att[(size_t)B_*NH_*S_*S_];
__device__ float g_ao [(size_t)T_*H_];
__device__ float g_xn2[(size_t)T_*H_];
__device__ float g_hg [(size_t)NE_*T_*I_];
__device__ float g_hu [(size_t)NE_*T_*I_];   // also reused as ye [NE][T][H]
__device__ int   g_tok[NE_*T_];
__device__ float g_wt [NE_*T_];
__device__ int   g_cnt[NE_];
__device__ int   g_texp [T_*2];
__device__ int   g_tslot[T_*2];
__device__ float g_tw   [T_*2];

// -------------------- helpers --------------------
__device__ __forceinline__ uint32_t f2tf(float f) {
    uint32_t r; asm("cvt.rna.tf32.f32 %0, %1;" : "=r"(r) : "f"(f)); return r;
}
__device__ __forceinline__ void mma8(float* c, const uint32_t* a, uint32_t b0, uint32_t b1) {
    asm volatile("mma.sync.aligned.m16n8k8.row.col.f32.tf32.tf32.f32 "
        "{%0,%1,%2,%3},{%4,%5,%6,%7},{%8,%9},{%0,%1,%2,%3};"
        : "+f"(c[0]), "+f"(c[1]), "+f"(c[2]), "+f"(c[3])
        : "r"(a[0]), "r"(a[1]), "r"(a[2]), "r"(a[3]), "r"(b0), "r"(b1));
}
__device__ __forceinline__ void ldsm4(uint32_t* r, uint32_t addr) {
    asm volatile("ldmatrix.sync.aligned.m8n8.x4.shared.b16 {%0,%1,%2,%3},[%4];"
        : "=r"(r[0]), "=r"(r[1]), "=r"(r[2]), "=r"(r[3]) : "r"(addr));
}
__device__ __forceinline__ void cpa16(uint32_t dst, const void* src) {
    asm volatile("cp.async.cg.shared.global [%0], [%1], 16;" :: "r"(dst), "l"(src));
}
__device__ __forceinline__ void cpa_commit() { asm volatile("cp.async.commit_group;"); }
__device__ __forceinline__ void cpa_wait1()  { asm volatile("cp.async.wait_group 1;" ::: "memory"); }
__device__ __forceinline__ uint32_t smem_u32(const void* p) {
    uint32_t a; asm("{ .reg .u64 t; cvta.to.shared.u64 t, %1; cvt.u32.u64 %0, t; }"
                    : "=r"(a) : "l"(p));
    return a;
}
// round-half-away to tf32 by bumping the raw fp32 bits (HMMA ignores low 13 bits)
#define RND_FRAG(r) { (r)[0]+=0x1000u; (r)[1]+=0x1000u; (r)[2]+=0x1000u; (r)[3]+=0x1000u; }

// -------------------- small kernels --------------------
__global__ void zero_cnt_k() { if (threadIdx.x < NE_) g_cnt[threadIdx.x] = 0; }

__global__ void rmsnorm_k(const float* __restrict__ x, const float* __restrict__ w,
                          float* __restrict__ o) {
    int t = blockIdx.x;
    const float* xr = x + (size_t)t * H_;
    float s = 0.f;
    for (int j = threadIdx.x; j < H_; j += blockDim.x) { float v = xr[j]; s += v * v; }
    __shared__ float red[32];
    for (int off = 16; off; off >>= 1) s += __shfl_xor_sync(0xffffffffu, s, off);
    if ((threadIdx.x & 31) == 0) red[threadIdx.x >> 5] = s;
    __syncthreads();
    if (threadIdx.x < 32) {
        float v = (threadIdx.x < (blockDim.x >> 5)) ? red[threadIdx.x] : 0.f;
        for (int off = 16; off; off >>= 1) v += __shfl_xor_sync(0xffffffffu, v, off);
        if (threadIdx.x == 0) red[0] = v;
    }
    __syncthreads();
    float inv = rsqrtf(red[0] / (float)H_ + EPS_);
    float* orow = o + (size_t)t * H_;
    for (int j = threadIdx.x; j < H_; j += blockDim.x) orow[j] = xr[j] * inv * w[j];
}

__global__ void add_residual_k(float* __restrict__ y, const float* __restrict__ x) {
    size_t i = (size_t)blockIdx.x * blockDim.x + threadIdx.x;
    float4* Y = (float4*)y; const float4* X = (const float4*)x;
    if (i < (size_t)T_ * H_ / 4) {
        float4 a = Y[i], b = X[i];
        a.x += b.x; a.y += b.y; a.z += b.z; a.w += b.w;
        Y[i] = a;
    }
}

__global__ void swiglu_all_k(float* __restrict__ hg, const float* __restrict__ hu) {
    int e = blockIdx.y;
    int cnt = g_cnt[e];
    float4* G = (float4*)(hg + (size_t)e * T_ * I_);
    const float4* U = (const float4*)(hu + (size_t)e * T_ * I_);
    size_t total = (size_t)cnt * (I_ / 4);
    size_t stride = (size_t)gridDim.x * blockDim.x;
    for (size_t i = (size_t)blockIdx.x * blockDim.x + threadIdx.x; i < total; i += stride) {
        float4 g = G[i], u = U[i];
        g.x = g.x / (1.f + __expf(-g.x)) * u.x;
        g.y = g.y / (1.f + __expf(-g.y)) * u.y;
        g.z = g.z / (1.f + __expf(-g.z)) * u.z;
        g.w = g.w / (1.f + __expf(-g.w)) * u.w;
        G[i] = g;
    }
}

// combine: out[t] += w0*ye[e0][s0] + w1*ye[e1][s1]
__global__ void combine_k(float* __restrict__ out, const float* __restrict__ ye) {
    int t = blockIdx.x;
    int e0 = g_texp[2*t], e1 = g_texp[2*t+1];
    int s0 = g_tslot[2*t], s1 = g_tslot[2*t+1];
    float w0 = g_tw[2*t], w1 = g_tw[2*t+1];
    const float4* y0 = (const float4*)(ye + ((size_t)e0 * T_ + s0) * H_);
    const float4* y1 = (const float4*)(ye + ((size_t)e1 * T_ + s1) * H_);
    float4* o = (float4*)(out + (size_t)t * H_);
    for (int j = threadIdx.x; j < H_ / 4; j += blockDim.x) {
        float4 a = o[j], p = y0[j], q = y1[j];
        a.x += w0 * p.x + w1 * q.x;
        a.y += w0 * p.y + w1 * q.y;
        a.z += w0 * p.z + w1 * q.z;
        a.w += w0 * p.w + w1 * q.w;
        o[j] = a;
    }
}

// ==================== tf32 MMA GEMM (3-stage cp.async + ldmatrix) ====================
// C[M,N] = A[M,K] * B[N,K]^T.
// Mode 0: z picks (B,C) from {B0/C0,B1/C1,B2/C2} (QKV / Wo).
// Mode 1: z = expert*2+{gate,up}; A rows gathered via token list; dense store.
// Mode 2: z = expert; dense A (per-expert hg); dense store into ye[e].
struct GArgs {
    const float* A;
    const float* B0; const float* B1; const float* B2;
    float* C0; float* C1; float* C2;
    int M, N, K, lda, ldb, ldc;
    const int* tok; const int* cntp;
    size_t aStride, bStride, cStride;
    int mode;
};

#define STG 3
#define BK 32
#define SROW 36
#define SOFF (128*SROW*4)              // 18432 B per matrix-stage
#define SMEM_BYTES (2*STG*SOFF)        // 110592 B

__global__ void __launch_bounds__(256, 2)
mma_gemm2(const GArgs args) {
    int z = blockIdx.z;
    const float* A = args.A;
    const float* B;
    float* C;
    const int* a_idx = nullptr;
    int cnt = args.M;

    if (args.mode == 0) {
        B = (z == 0) ? args.B0 : (z == 1 ? args.B1 : args.B2);
        C = (z == 0) ? args.C0 : (z == 1 ? args.C1 : args.C2);
    } else if (args.mode == 1) {
        int e = z >> 1;
        B = ((z & 1) ? args.B1 : args.B0) + (size_t)e * args.bStride;
        C = ((z & 1) ? args.C1 : args.C0) + (size_t)e * args.cStride;
        a_idx = args.tok + e * T_;
        cnt = args.cntp[e];
    } else {
        int e = z;
        A = args.A + (size_t)e * args.aStride;
        B = args.B0 + (size_t)e * args.bStride;
        C = args.C0 + (size_t)e * args.cStride;
        cnt = args.cntp[e];
    }

    int m0 = blockIdx.y * 128, n0 = blockIdx.x * 128;
    if (m0 >= cnt) return;

    extern __shared__ float sm[];
    uint32_t sA = smem_u32(sm);
    uint32_t sB = sA + STG * SOFF;

    int tid = threadIdx.x;
    int lane = tid & 31, w = tid >> 5;
    int wm = (w & 3) * 32, wn = (w >> 2) * 64;

    int lrow = tid >> 3;
    int lcol = (tid & 7) * 4;
    const float* gA[4]; const float* gB[4];
    uint32_t stA[4], stB[4];
#pragma unroll
    for (int rr = 0; rr < 4; rr++) {
        int mr = m0 + lrow + rr * 32;
        int grow;
        if (a_idx) grow = (mr < cnt) ? a_idx[mr] : 0;
        else       grow = mr;
        gA[rr] = A + (size_t)grow * args.lda + lcol;
        gB[rr] = B + (size_t)(n0 + lrow + rr * 32) * args.ldb + lcol;
        stA[rr] = sA + ((lrow + rr * 32) * SROW + lcol) * 4;
        stB[rr] = sB + ((lrow + rr * 32) * SROW + lcol) * 4;
    }

    uint32_t aAddr = sA + ((wm + (lane & 15)) * SROW + 4 * ((lane >> 4) & 1)) * 4;
    uint32_t bAddr = sB + ((wn + (lane & 7) + 8 * ((lane >> 4) & 1)) * SROW
                           + 4 * ((lane >> 3) & 1)) * 4;

    float acc[2][8][4];
#pragma unroll
    for (int i = 0; i < 2; i++)
#pragma unroll
        for (int j = 0; j < 8; j++)
#pragma unroll
            for (int q = 0; q < 4; q++) acc[i][j][q] = 0.f;

    int nk = args.K / BK;

    // prefetch stages 0 and 1
#pragma unroll
    for (int s = 0; s < 2; s++) {
        int kb = s * BK;
#pragma unroll
        for (int rr = 0; rr < 4; rr++) {
            cpa16(stA[rr] + s * SOFF, gA[rr] + kb);
            cpa16(stB[rr] + s * SOFF, gB[rr] + kb);
        }
        cpa_commit();
    }

    for (int kt = 0; kt < nk; kt++) {
        cpa_wait1();
        __syncthreads();
        if (kt + 2 < nk) {
            int kb = (kt + 2) * BK;
            uint32_t off = ((kt + 2) % 3) * SOFF;
#pragma unroll
            for (int rr = 0; rr < 4; rr++) {
                cpa16(stA[rr] + off, gA[rr] + kb);
                cpa16(stB[rr] + off, gB[rr] + kb);
            }
        }
        cpa_commit();

        uint32_t soff = (kt % 3) * SOFF;
#pragma unroll
        for (int ks = 0; ks < 4; ks++) {
            uint32_t koff = soff + ks * 32;
            uint32_t a[2][4];
            ldsm4(a[0], aAddr + koff);
            ldsm4(a[1], aAddr + koff + 16 * SROW * 4);
            RND_FRAG(a[0]); RND_FRAG(a[1]);
            uint32_t b[4][4];
#pragma unroll
            for (int jp = 0; jp < 4; jp++) {
                ldsm4(b[jp], bAddr + koff + jp * (16 * SROW * 4));
                RND_FRAG(b[jp]);
            }
#pragma unroll
            for (int im = 0; im < 2; im++)
#pragma unroll
                for (int jn = 0; jn < 8; jn++)
                    mma8(acc[im][jn], a[im], b[jn >> 1][(jn & 1) * 2], b[jn >> 1][(jn & 1) * 2 + 1]);
        }
    }

    int cg = 2 * (lane & 3);
#pragma unroll
    for (int im = 0; im < 2; im++) {
#pragma unroll
        for (int half = 0; half < 2; half++) {
            int m = m0 + wm + im * 16 + (lane >> 2) + half * 8;
            if (m >= cnt) continue;
            float* cp = C + (size_t)m * args.ldc + n0 + wn + cg;
#pragma unroll
            for (int jn = 0; jn < 8; jn++) {
                float2 o;
                o.x = acc[im][jn][half * 2 + 0];
                o.y = acc[im][jn][half * 2 + 1];
                *((float2*)(cp + jn * 8)) = o;
            }
        }
    }
}

// ==================== causal scores (pipelined ldsm version) ====================
__global__ void __launch_bounds__(256, 2)
attn_score_mma2(const float* __restrict__ Q, const float* __restrict__ Kt) {
    int bh = blockIdx.z, b = bh >> 4, h = bh & 15;
    int m0 = blockIdx.y * 128, n0 = blockIdx.x * 128;
    if (n0 > m0) return;

    const float* Qb = Q + (size_t)b * S_ * H_ + h * HD_;
    const float* Kb = Kt + (size_t)b * S_ * H_ + h * HD_;
    float* Sb = g_att + (size_t)bh * S_ * S_;

    extern __shared__ float sm[];
    uint32_t sA = smem_u32(sm);
    uint32_t sB = sA + STG * SOFF;

    int tid = threadIdx.x;
    int lane = tid & 31, w = tid >> 5;
    int wm = (w & 3) * 32, wn = (w >> 2) * 64;

    int lrow = tid >> 3;
    int lcol = (tid & 7) * 4;
    const float* gA[4]; const float* gB[4];
    uint32_t stA[4], stB[4];
#pragma unroll
    for (int rr = 0; rr < 4; rr++) {
        gA[rr] = Qb + (size_t)(m0 + lrow + rr * 32) * H_ + lcol;
        gB[rr] = Kb + (size_t)(n0 + lrow + rr * 32) * H_ + lcol;
        stA[rr] = sA + ((lrow + rr * 32) * SROW + lcol) * 4;
        stB[rr] = sB + ((lrow + rr * 32) * SROW + lcol) * 4;
    }

    uint32_t aAddr = sA + ((wm + (lane & 15)) * SROW + 4 * ((lane >> 4) & 1)) * 4;
    uint32_t bAddr = sB + ((wn + (lane & 7) + 8 * ((lane >> 4) & 1)) * SROW
                           + 4 * ((lane >> 3) & 1)) * 4;

    float acc[2][8][4];
#pragma unroll
    for (int i = 0; i < 2; i++)
#pragma unroll
        for (int j = 0; j < 8; j++)
#pragma unroll
            for (int q = 0; q < 4; q++) acc[i][j][q] = 0.f;

    const int nk = HD_ / BK;   // 4

#pragma unroll
    for (int s = 0; s < 2; s++) {
        int kb = s * BK;
#pragma unroll
        for (int rr = 0; rr < 4; rr++) {
            cpa16(stA[rr] + s * SOFF, gA[rr] + kb);
            cpa16(stB[rr] + s * SOFF, gB[rr] + kb);
        }
        cpa_commit();
    }

    for (int kt = 0; kt < nk; kt++) {
        cpa_wait1();
        __syncthreads();
        if (kt + 2 < nk) {
            int kb = (kt + 2) * BK;
            uint32_t off = ((kt + 2) % 3) * SOFF;
#pragma unroll
            for (int rr = 0; rr < 4; rr++) {
                cpa16(stA[rr] + off, gA[rr] + kb);
                cpa16(stB[rr] + off, gB[rr] + kb);
            }
        }
        cpa_commit();

        uint32_t soff = (kt % 3) * SOFF;
#pragma unroll
        for (int ks = 0; ks < 4; ks++) {
            uint32_t koff = soff + ks * 32;
            uint32_t a[2][4];
            ldsm4(a[0], aAddr + koff);
            ldsm4(a[1], aAddr + koff + 16 * SROW * 4);
            RND_FRAG(a[0]); RND_FRAG(a[1]);
            uint32_t b2[4][4];
#pragma unroll
            for (int jp = 0; jp < 4; jp++) {
                ldsm4(b2[jp], bAddr + koff + jp * (16 * SROW * 4));
                RND_FRAG(b2[jp]);
            }
#pragma unroll
            for (int im = 0; im < 2; im++)
#pragma unroll
                for (int jn = 0; jn < 8; jn++)
                    mma8(acc[im][jn], a[im], b2[jn >> 1][(jn & 1) * 2], b2[jn >> 1][(jn & 1) * 2 + 1]);
        }
    }

    int cg = 2 * (lane & 3);
#pragma unroll
    for (int im = 0; im < 2; im++) {
#pragma unroll
        for (int half = 0; half < 2; half++) {
            int i = m0 + wm + im * 16 + (lane >> 2) + half * 8;
            float* cp = Sb + (size_t)i * S_ + n0 + wn + cg;
#pragma unroll
            for (int jn = 0; jn < 8; jn++) {
                int j = n0 + wn + cg + jn * 8;
                float2 o;
                o.x = (j     > i) ? -1e30f : acc[im][jn][half * 2 + 0] * ATT_SCALE;
                o.y = (j + 1 > i) ? -1e30f : acc[im][jn][half * 2 + 1] * ATT_SCALE;
                *((float2*)(cp + jn * 8)) = o;
            }
        }
    }
}

// ==================== adaptive row softmax ====================
__global__ void softmax_k() {
    int r = blockIdx.x & (S_ - 1);
    float* row = g_att + (size_t)blockIdx.x * S_;
    int len = r + 1;
    int tid = threadIdx.x;
    float v[8];
    float mx = -1e30f;
#pragma unroll
    for (int i = 0; i < 8; i++) {
        int j = tid + i * 256;
        v[i] = (j < len) ? row[j] : -1e30f;
        mx = fmaxf(mx, v[i]);
    }
    __shared__ float red[32];
    for (int off = 16; off; off >>= 1) mx = fmaxf(mx, __shfl_xor_sync(0xffffffffu, mx, off));
    if ((tid & 31) == 0) red[tid >> 5] = mx;
    __syncthreads();
    if (tid < 32) {
        float m2 = (tid < 8) ? red[tid] : -1e38f;
        for (int off = 16; off; off >>= 1) m2 = fmaxf(m2, __shfl_xor_sync(0xffffffffu, m2, off));
        if (tid == 0) red[0] = m2;
    }
    __syncthreads();
    mx = red[0];
    float s = 0.f;
#pragma unroll
    for (int i = 0; i < 8; i++) { v[i] = __expf(v[i] - mx); s += v[i]; }
    __syncthreads();
    for (int off = 16; off; off >>= 1) s += __shfl_xor_sync(0xffffffffu, s, off);
    if ((tid & 31) == 0) red[tid >> 5] = s;
    __syncthreads();
    if (tid < 32) {
        float s2 = (tid < 8) ? red[tid] : 0.f;
        for (int off = 16; off; off >>= 1) s2 += __shfl_xor_sync(0xffffffffu, s2, off);
        if (tid == 0) red[0] = s2;
    }
    __syncthreads();
    float inv = 1.f / red[0];
#pragma unroll
    for (int i = 0; i < 8; i++) {
        int j = tid + i * 256;
        if (j < len) row[j] = v[i] * inv;
    }
    int kmax = ((r >> 7) + 1) << 7;
    for (int j = len + tid; j < kmax; j += 256) row[j] = 0.f;
}

// ==================== P @ V (tf32 MMA, causal-truncated) ====================
__global__ void __launch_bounds__(256)
attn_pv_mma(const float* __restrict__ V) {
    int bh = blockIdx.y, b = bh >> 4, h = bh & 15;
    int m0 = blockIdx.x * 128;
    const float* Pb = g_att + (size_t)bh * S_ * S_;
    const float* Vb = V + (size_t)b * S_ * H_ + h * HD_;
    float* Ob = g_ao + (size_t)b * S_ * H_ + h * HD_;

    __shared__ uint32_t As[128][20];
    __shared__ uint32_t Bs[16][136];
    int tid = threadIdx.x;
    int lane = tid & 31, w = tid >> 5;
    int wm = (w & 3) * 32, wn = (w >> 2) * 64;
    int r1 = tid >> 2, c4 = (tid & 3) * 4;
    int kr = tid >> 5, nc4 = (tid & 31) * 4;

    const float* aP[2] = { Pb + (size_t)(m0 + r1) * S_ + c4,
                           Pb + (size_t)(m0 + r1 + 64) * S_ + c4 };

    float acc[2][8][4];
#pragma unroll
    for (int i = 0; i < 2; i++)
#pragma unroll
        for (int j = 0; j < 8; j++)
#pragma unroll
            for (int q = 0; q < 4; q++) acc[i][j][q] = 0.f;

    int kmax = m0 + 128;
    for (int kb = 0; kb < kmax; kb += 16) {
#pragma unroll
        for (int h2 = 0; h2 < 2; h2++) {
            float4 av = *(const float4*)(aP[h2] + kb);
            int rr = r1 + h2 * 64;
            As[rr][c4 + 0] = f2tf(av.x); As[rr][c4 + 1] = f2tf(av.y);
            As[rr][c4 + 2] = f2tf(av.z); As[rr][c4 + 3] = f2tf(av.w);
            float4 bv = *(const float4*)(Vb + (size_t)(kb + kr + h2 * 8) * H_ + nc4);
            int kk = kr + h2 * 8;
            Bs[kk][nc4 + 0] = f2tf(bv.x); Bs[kk][nc4 + 1] = f2tf(bv.y);
            Bs[kk][nc4 + 2] = f2tf(bv.z); Bs[kk][nc4 + 3] = f2tf(bv.w);
        }
        __syncthreads();
#pragma unroll
        for (int ks = 0; ks < 2; ks++) {
            int k0 = ks * 8 + (lane & 3);
            uint32_t af[2][4];
#pragma unroll
            for (int im = 0; im < 2; im++) {
                int mr = wm + im * 16 + (lane >> 2);
                af[im][0] = As[mr][k0];     af[im][1] = As[mr + 8][k0];
                af[im][2] = As[mr][k0 + 4]; af[im][3] = As[mr + 8][k0 + 4];
            }
#pragma unroll
            for (int jn = 0; jn < 8; jn++) {
                int nr = wn + jn * 8 + (lane >> 2);
                uint32_t b0 = Bs[k0][nr], b1 = Bs[k0 + 4][nr];
                mma8(acc[0][jn], af[0], b0, b1);
                mma8(acc[1][jn], af[1], b0, b1);
            }
        }
        __syncthreads();
    }

    int cg = 2 * (lane & 3);
#pragma unroll
    for (int im = 0; im < 2; im++) {
#pragma unroll
        for (int half = 0; half < 2; half++) {
            int m = m0 + wm + im * 16 + (lane >> 2) + half * 8;
            float* cp = Ob + (size_t)m * H_ + wn + cg;
#pragma unroll
            for (int jn = 0; jn < 8; jn++) {
                float2 o;
                o.x = acc[im][jn][half * 2 + 0];
                o.y = acc[im][jn][half * 2 + 1];
                *((float2*)(cp + jn * 8)) = o;
            }
        }
    }
}

// ==================== router ====================
__global__ void router_k(const float* __restrict__ xn2, const float* __restrict__ Wr) {
    int t = blockIdx.x * (blockDim.x >> 5) + (threadIdx.x >> 5);
    if (t >= T_) return;
    int lane = threadIdx.x & 31;
    const float* xr = xn2 + (size_t)t * H_;
    float s[NE_];
#pragma unroll
    for (int e = 0; e < NE_; e++) s[e] = 0.f;
    for (int j = lane; j < H_; j += 32) {
        float xv = xr[j];
#pragma unroll
        for (int e = 0; e < NE_; e++) s[e] += xv * Wr[e * H_ + j];
    }
#pragma unroll
    for (int e = 0; e < NE_; e++)
        for (int off = 16; off; off >>= 1) s[e] += __shfl_xor_sync(0xffffffffu, s[e], off);
    if (lane == 0) {
        int b0 = 0;
#pragma unroll
        for (int e = 1; e < NE_; e++) if (s[e] > s[b0]) b0 = e;
        int b1 = -1;
#pragma unroll
        for (int e = 0; e < NE_; e++) {
            if (e == b0) continue;
            if (b1 < 0 || s[e] > s[b1]) b1 = e;
        }
        float m = s[b0];
        float e0 = __expf(s[b0] - m), e1 = __expf(s[b1] - m);
        float inv = 1.f / (e0 + e1);
        int pos0 = atomicAdd(&g_cnt[b0], 1);
        g_tok[b0 * T_ + pos0] = t;
        int pos1 = atomicAdd(&g_cnt[b1], 1);
        g_tok[b1 * T_ + pos1] = t;
        g_texp [2*t] = b0;  g_texp [2*t+1] = b1;
        g_tslot[2*t] = pos0; g_tslot[2*t+1] = pos1;
        g_tw   [2*t] = e0 * inv; g_tw[2*t+1] = e1 * inv;
    }
}

// ==================== host ====================
extern "C" void kernel_launch(void* const* d_in, const int* in_sizes, int n_in,
                              void* d_out, int out_size) {
    const float* x    = (const float*)d_in[0];
    const float* Wq   = (const float*)d_in[1];
    const float* Wk   = (const float*)d_in[2];
    const float* Wv   = (const float*)d_in[3];
    const float* Wo   = (const float*)d_in[4];
    const float* wln1 = (const float*)d_in[5];
    const float* wln2 = (const float*)d_in[6];
    const float* Wr   = (const float*)d_in[7];
    const float* Wg   = (const float*)d_in[8];
    const float* Wu   = (const float*)d_in[9];
    const float* Wd   = (const float*)d_in[10];
    float* out = (float*)d_out;

    float *p_xn, *p_q, *p_k, *p_v, *p_ao, *p_xn2, *p_hg, *p_hu;
    int *p_tok, *p_cnt;
    cudaGetSymbolAddress((void**)&p_xn,  g_xn);
    cudaGetSymbolAddress((void**)&p_q,   g_q);
    cudaGetSymbolAddress((void**)&p_k,   g_k);
    cudaGetSymbolAddress((void**)&p_v,   g_v);
    cudaGetSymbolAddress((void**)&p_ao,  g_ao);
    cudaGetSymbolAddress((void**)&p_xn2, g_xn2);
    cudaGetSymbolAddress((void**)&p_hg,  g_hg);
    cudaGetSymbolAddress((void**)&p_hu,  g_hu);
    cudaGetSymbolAddress((void**)&p_tok, g_tok);
    cudaGetSymbolAddress((void**)&p_cnt, g_cnt);

    static int smem_set = 0;
    if (!smem_set) {
        cudaFuncSetAttribute(mma_gemm2, cudaFuncAttributeMaxDynamicSharedMemorySize, SMEM_BYTES);
        cudaFuncSetAttribute(attn_score_mma2, cudaFuncAttributeMaxDynamicSharedMemorySize, SMEM_BYTES);
        smem_set = 1;
    }

    zero_cnt_k<<<1, 32>>>();
    rmsnorm_k<<<T_, 256>>>(x, wln1, p_xn);

    // QKV fused launch
    {
        GArgs a = {};
        a.A = p_xn; a.B0 = Wq; a.B1 = Wk; a.B2 = Wv;
        a.C0 = p_q; a.C1 = p_k; a.C2 = p_v;
        a.M = T_; a.N = H_; a.K = H_; a.lda = H_; a.ldb = H_; a.ldc = H_;
        a.mode = 0;
        mma_gemm2<<<dim3(H_ / 128, T_ / 128, 3), 256, SMEM_BYTES>>>(a);
    }

    attn_score_mma2<<<dim3(S_ / 128, S_ / 128, B_ * NH_), 256, SMEM_BYTES>>>(p_q, p_k);
    softmax_k<<<B_ * NH_ * S_, 256>>>();
    attn_pv_mma<<<dim3(S_ / 128, B_ * NH_), 256>>>(p_v);

    // Wo projection
    {
        GArgs a = {};
        a.A = p_ao; a.B0 = Wo; a.C0 = out;
        a.M = T_; a.N = H_; a.K = H_; a.lda = H_; a.ldb = H_; a.ldc = H_;
        a.mode = 0;
        mma_gemm2<<<dim3(H_ / 128, T_ / 128, 1), 256, SMEM_BYTES>>>(a);
    }
    add_residual_k<<<(T_ * H_ / 4 + 255) / 256, 256>>>(out, x);

    rmsnorm_k<<<T_, 256>>>(out, wln2, p_xn2);
    router_k<<<T_ / 8, 256>>>(p_xn2, Wr);

    // MoE gate+up (gathered A)
    {
        GArgs a = {};
        a.A = p_xn2; a.B0 = Wg; a.B1 = Wu;
        a.C0 = p_hg; a.C1 = p_hu;
        a.M = T_; a.N = I_; a.K = H_; a.lda = H_; a.ldb = H_; a.ldc = I_;
        a.tok = p_tok; a.cntp = p_cnt;
        a.bStride = (size_t)I_ * H_; a.cStride = (size_t)T_ * I_;
        a.mode = 1;
        mma_gemm2<<<dim3(I_ / 128, T_ / 128, 2 * NE_), 256, SMEM_BYTES>>>(a);
    }

    swiglu_all_k<<<dim3(512, NE_), 256>>>(p_hg, p_hu);

    // MoE down: dense per-expert store into ye (reuses g_hu), then combine
    {
        GArgs a = {};
        a.A = p_hg; a.B0 = Wd; a.C0 = p_hu;
        a.M = T_; a.N = H_; a.K = I_; a.lda = I_; a.ldb = I_; a.ldc = H_;
        a.cntp = p_cnt;
        a.aStride = (size_t)T_ * I_; a.bStride = (size_t)H_ * I_;
        a.cStride = (size_t)T_ * H_;
        a.mode = 2;
        mma_gemm2<<<dim3(H_ / 128, T_ / 128, NE_), 256, SMEM_BYTES>>>(a);
    }

    combine_k<<<T_, 256>>>(out, p_hu);
}